// round 2
// baseline (speedup 1.0000x reference)
#include <cuda_runtime.h>
#include <math.h>
#include <stdint.h>

#define BATCH    2048
#define NCLS     100
#define NHALF    1024      // BATCH/2
#define FH       64        // FEATURE_NUMS/2
#define O        9         // POLICY_NUMS + 2
#define NBIN     16

// ---------------- scratch (device globals; no allocation) ----------------
__device__ double g_ce, g_kl;
// per-k stats, layout [k][q], q: 0 Su,1 Su2,2 Sv,3 Sv2,4 Sb,5 Sa,6 Sb2,7 Sa2
__device__ double g_acc[O * 8];
__device__ double g_SA[8 * NBIN], g_SB[8 * NBIN];
__device__ int    g_c1[8 * NBIN], g_c2[8 * NBIN];

// ---------------- kernel 0: zero scratch ----------------
__global__ void k_zero() {
    int t = threadIdx.x;
    if (t == 0) { g_ce = 0.0; g_kl = 0.0; }
    if (t < O * 8) g_acc[t] = 0.0;
    for (int i = t; i < 8 * NBIN; i += blockDim.x) {
        g_SA[i] = 0.0; g_SB[i] = 0.0; g_c1[i] = 0; g_c2[i] = 0;
    }
}

// ---------------- kernel 1: logits CE + KL ----------------
// one warp per row; 8 warps/block; 256 blocks covers 2048 rows
__global__ __launch_bounds__(256) void k_logits(
    const float* __restrict__ sl, const float* __restrict__ tl,
    const int* __restrict__ tg)
{
    __shared__ double s_ce, s_kl;
    if (threadIdx.x == 0) { s_ce = 0.0; s_kl = 0.0; }
    __syncthreads();

    int row  = blockIdx.x * 8 + (threadIdx.x >> 5);
    int lane = threadIdx.x & 31;
    const float* s = sl + row * NCLS;
    const float* t = tl + row * NCLS;

    float sv[4], tv[4];
#pragma unroll
    for (int i = 0; i < 4; i++) {
        int c = lane + 32 * i;
        bool val = c < NCLS;
        sv[i] = val ? s[c] : -INFINITY;
        tv[i] = val ? t[c] : -INFINITY;
    }
    float smax = fmaxf(fmaxf(sv[0], sv[1]), fmaxf(sv[2], sv[3]));
    float tmax = fmaxf(fmaxf(tv[0], tv[1]), fmaxf(tv[2], tv[3]));
#pragma unroll
    for (int o = 16; o; o >>= 1) {
        smax = fmaxf(smax, __shfl_xor_sync(0xffffffffu, smax, o));
        tmax = fmaxf(tmax, __shfl_xor_sync(0xffffffffu, tmax, o));
    }

    float S1 = 0.f, S4 = 0.f, T4 = 0.f;
    float te[4];
#pragma unroll
    for (int i = 0; i < 4; i++) {
        int c = lane + 32 * i;
        if (c < NCLS) {
            float ds = sv[i] - smax;
            S1 += __expf(ds);              // fast exp ok: args <= 0, smooth sums
            S4 += __expf(ds * 0.25f);
            te[i] = __expf((tv[i] - tmax) * 0.25f);
            T4 += te[i];
        } else te[i] = 0.f;
    }
#pragma unroll
    for (int o = 16; o; o >>= 1) {
        S1 += __shfl_xor_sync(0xffffffffu, S1, o);
        S4 += __shfl_xor_sync(0xffffffffu, S4, o);
        T4 += __shfl_xor_sync(0xffffffffu, T4, o);
    }
    float lS1 = logf(S1), lS4 = logf(S4), lT4 = logf(T4);
    float invT4 = 1.0f / T4;

    // KL row: sum_c q * (logq - slogp)
    float kl = 0.f;
#pragma unroll
    for (int i = 0; i < 4; i++) {
        int c = lane + 32 * i;
        if (c < NCLS) {
            float a   = (tv[i] - tmax) * 0.25f;
            float q   = te[i] * invT4;
            float slp = (sv[i] - smax) * 0.25f - lS4;
            kl += q * ((a - lT4) - slp);
        }
    }
#pragma unroll
    for (int o = 16; o; o >>= 1) kl += __shfl_down_sync(0xffffffffu, kl, o);

    // CE row: logsumexp(s) - s[label]
    int label = tg[row * 8];
    int idx = label >> 5;
    float cand = (idx == 0) ? sv[0] : (idx == 1) ? sv[1] : (idx == 2) ? sv[2] : sv[3];
    float slab = __shfl_sync(0xffffffffu, cand, label & 31);

    if (lane == 0) {
        atomicAdd(&s_ce, (double)(smax + lS1) - (double)slab);
        atomicAdd(&s_kl, (double)kl);
    }
    __syncthreads();
    if (threadIdx.x == 0) {
        atomicAdd(&g_ce, s_ce);
        atomicAdd(&g_kl, s_kl);
    }
}

// ---------------- kernel 2: policy GEMVs + closed-form stats ----------------
// thread j handles pair j (even row -> A, odd row -> B); 16 blocks x 64 thr = 1024
__global__ __launch_bounds__(64) void k_policy(
    const float* __restrict__ sp, const float* __restrict__ tp,
    const float* __restrict__ W1, const float* __restrict__ W2,
    const int*  __restrict__ tg)
{
    __shared__ float W2s[O * 2 * FH], W1s[O * 2 * FH];
    __shared__ double sacc[O * 8];
    __shared__ double sSA[8 * NBIN], sSB[8 * NBIN];
    __shared__ int    sc1[8 * NBIN], sc2[8 * NBIN];

    int tid = threadIdx.x;
    for (int i = tid; i < O * 2 * FH; i += 64) { W2s[i] = W2[i]; W1s[i] = W1[i]; }
    for (int i = tid; i < O * 8; i += 64) sacc[i] = 0.0;
    for (int i = tid; i < 8 * NBIN; i += 64) { sSA[i] = 0.0; sSB[i] = 0.0; sc1[i] = 0; sc2[i] = 0; }
    __syncthreads();

    int j = blockIdx.x * 64 + tid;           // 0..1023
    const float* se  = sp + (2 * j) * FH;    // student even  -> sA
    const float* so  = se + FH;              // student odd   -> sB
    const float* tee = tp + (2 * j) * FH;    // teacher even  -> tA
    const float* to  = tee + FH;             // teacher odd   -> tB

    float as[O] = {}, bs[O] = {}, at[O] = {}, bt[O] = {};
#pragma unroll
    for (int c = 0; c < FH; c += 4) {
        float4 a = *(const float4*)(se + c);
        float4 b = *(const float4*)(so + c);
        float4 x = *(const float4*)(tee + c);
        float4 y = *(const float4*)(to + c);
#pragma unroll
        for (int k = 0; k < O; k++) {
            const float* w2l = W2s + k * 2 * FH + c;
            const float* w2h = w2l + FH;
            const float* w1l = W1s + k * 2 * FH + c;
            const float* w1h = w1l + FH;
            as[k] += a.x * w2l[0] + a.y * w2l[1] + a.z * w2l[2] + a.w * w2l[3];
            bs[k] += b.x * w2h[0] + b.y * w2h[1] + b.z * w2h[2] + b.w * w2h[3];
            at[k] += x.x * w1l[0] + x.y * w1l[1] + x.z * w1l[2] + x.w * w1l[3];
            bt[k] += y.x * w1h[0] + y.y * w1h[1] + y.z * w1h[2] + y.w * w1h[3];
        }
    }

    // per-k reductions (u = sB - tB over i, v = sA - tA over j)
#pragma unroll
    for (int k = 0; k < O; k++) {
        float u = bs[k] - bt[k];
        float v = as[k] - at[k];
        double r[8];
        r[0] = u;            r[1] = (double)u * u;
        r[2] = v;            r[3] = (double)v * v;
        r[4] = bs[k];        r[5] = as[k];
        r[6] = (double)bs[k] * bs[k];
        r[7] = (double)as[k] * as[k];
#pragma unroll
        for (int q = 0; q < 8; q++) {
#pragma unroll
            for (int o = 16; o; o >>= 1)
                r[q] += __shfl_down_sync(0xffffffffu, r[q], o);
        }
        if ((tid & 31) == 0) {
#pragma unroll
            for (int q = 0; q < 8; q++) atomicAdd(&sacc[k * 8 + q], r[q]);
        }
    }

    // binned match sums: target column tc pairs with output column tc+1
    const int* t1r = tg + (2 * j) * 8;       // even target rows (A side)
    const int* t2r = tg + (2 * j + 1) * 8;   // odd  target rows (B side)
#pragma unroll
    for (int tc = 0; tc < 8; tc++) {
        int v1 = t1r[tc] & (NBIN - 1);
        int v2 = t2r[tc] & (NBIN - 1);
        atomicAdd(&sSA[tc * NBIN + v1], (double)as[tc + 1]);
        atomicAdd(&sc1[tc * NBIN + v1], 1);
        atomicAdd(&sSB[tc * NBIN + v2], (double)bs[tc + 1]);
        atomicAdd(&sc2[tc * NBIN + v2], 1);
    }
    __syncthreads();

    // flush to global
    for (int i = tid; i < O * 8; i += 64) atomicAdd(&g_acc[i], sacc[i]);
    for (int i = tid; i < 8 * NBIN; i += 64) {
        atomicAdd(&g_SA[i], sSA[i]);
        atomicAdd(&g_SB[i], sSB[i]);
        atomicAdd(&g_c1[i], sc1[i]);
        atomicAdd(&g_c2[i], sc2[i]);
    }
}

// ---------------- kernel 3: final combine ----------------
__global__ __launch_bounds__(128) void k_final(
    const float* __restrict__ b1, const float* __restrict__ b2,
    float* __restrict__ out)
{
    __shared__ double m_sh[128], p_sh[128];
    int tid = threadIdx.x;
    int tc = tid >> 4;
    {
        double c1 = (double)g_c1[tid];
        double c2 = (double)g_c2[tid];
        double bias = (double)b2[tc + 1];
        // Sum over matching pairs of (sB_i + sA_j + bias):
        //   cnt1(even)*SBbin(odd) + cnt2(odd)*SAbin(even) + cnt1*cnt2*bias
        m_sh[tid] = c1 * g_SB[tid] + c2 * g_SA[tid] + c1 * c2 * bias;
        p_sh[tid] = c1 * c2;
    }
    __syncthreads();

    if (tid == 0) {
        double matchS[8], pairS[8];
#pragma unroll
        for (int t = 0; t < 8; t++) {
            double ms = 0.0, ps = 0.0;
#pragma unroll
            for (int v = 0; v < NBIN; v++) { ms += m_sh[t * NBIN + v]; ps += p_sh[t * NBIN + v]; }
            matchS[t] = ms; pairS[t] = ps;
        }

        const double n = 1024.0, N2 = n * n;
        double acc[O * 8];
#pragma unroll
        for (int i = 0; i < O * 8; i++) acc[i] = g_acc[i];
        double cb1[O], cb2[O];
#pragma unroll
        for (int k = 0; k < O; k++) { cb1[k] = (double)b1[k]; cb2[k] = (double)b2[k]; }

        // --- pairwise-MSE (kl part of policy loss), fully separable ---
        double D2[O];
#pragma unroll
        for (int k = 0; k < O; k++) {
            double Su = acc[k*8+0], Su2 = acc[k*8+1], Sv = acc[k*8+2], Sv2 = acc[k*8+3];
            double ck = cb2[k] - cb1[k];
            D2[k] = n * Su2 + n * Sv2 + 2.0 * Su * Sv
                  + 2.0 * ck * n * (Su + Sv) + N2 * ck * ck;
        }
        double sumDP = 0.0;
#pragma unroll
        for (int k = 2; k < O; k++) sumDP += D2[k];
        double klp = D2[0] / N2 + 0.5 * D2[1] / N2 + 0.001 * sumDP / (N2 * 7.0);

        // --- ce part of policy loss ---
        // gI/gC positive values, computed exactly as the fp32 reference would
        double gId = (double)((1.0f / 1023.0f + 1.0f) - 1.0f / 1023.0f);
        double gCp = (double)((1.0f / 99.0f + 1.0f) - 1.0f / 99.0f);

        double Sb0 = acc[0*8+4], Sa0 = acc[0*8+5];
        double E1 = (n * gId * log(gId) - gId * (Sb0 + Sa0 + n * cb2[0])) / N2;

        double E2 = 0.5 * (pairS[0] * gCp * log(gCp) - gCp * matchS[0]) / N2;

        double E3 = 0.0;
#pragma unroll
        for (int m = 0; m < 7; m++) {
            int k = m + 2, t = m + 1;
            double Sb = acc[k*8+4], Sa = acc[k*8+5], Sb2 = acc[k*8+6], Sa2 = acc[k*8+7];
            double ck = cb2[k];
            double Sp2 = n * Sb2 + n * Sa2 + 2.0 * Sb * Sa
                       + 2.0 * ck * n * (Sb + Sa) + N2 * ck * ck;
            double Sp  = n * (Sb + Sa) + N2 * ck;
            double Spg = 2.0 * matchS[t] - Sp;       // g = 2*Teq - 1
            E3 += Sp2 - 2.0 * Spg + N2;              // + sum(g^2) = N2
        }
        E3 *= 0.001 / (N2 * 7.0);

        double policy = klp + E1 + E2 + E3;
        double ce_logits = g_ce / (double)BATCH;
        double kl_logits = g_kl / ((double)BATCH * (double)NCLS) * 16.0;  // * KL_TEMP^2

        out[0] = (float)(ce_logits + kl_logits + policy);
    }
}

// ---------------- launch ----------------
extern "C" void kernel_launch(void* const* d_in, const int* in_sizes, int n_in,
                              void* d_out, int out_size)
{
    const float* sl = (const float*)d_in[0];   // student_logits (2048,100)
    const float* tl = (const float*)d_in[1];   // teacher_logits (2048,100)
    const float* sp = (const float*)d_in[2];   // student_policy (2048,64)
    const float* tp = (const float*)d_in[3];   // teacher_policy (2048,64)
    const float* W1 = (const float*)d_in[4];   // (9,128)
    const float* b1 = (const float*)d_in[5];   // (9,)
    const float* W2 = (const float*)d_in[6];   // (9,128)
    const float* b2 = (const float*)d_in[7];   // (9,)
    const int*   tg = (const int*)d_in[8];     // (2048,1,8)

    k_zero<<<1, 256>>>();
    k_logits<<<BATCH / 8, 256>>>(sl, tl, tg);
    k_policy<<<16, 64>>>(sp, tp, W1, W2, tg);
    k_final<<<1, 128>>>(b1, b2, (float*)d_out);
}

// round 3
// speedup vs baseline: 1.2969x; 1.2969x over previous
#include <cuda_runtime.h>
#include <math.h>
#include <stdint.h>

#define BATCH    2048
#define NCLS     100
#define FH       64        // FEATURE_NUMS/2
#define O        9         // POLICY_NUMS + 2
#define NBIN     16
#define LBLK     256       // logits blocks (8 rows each)
#define PBLK     4         // policy blocks (256 pairs each)
#define NBLOCKS  (LBLK + PBLK)

// ---------------- scratch (device globals; zero-initialized at load,
//                  re-zeroed by the last block each run) ----------------
__device__ double g_ce, g_kl;
// per-k stats, layout [k][q], q: 0 Su,1 Su2,2 Sv,3 Sv2,4 Sb,5 Sa,6 Sb2,7 Sa2
__device__ double g_acc[O * 8];
__device__ double g_SA[8 * NBIN], g_SB[8 * NBIN];
__device__ int    g_c1[8 * NBIN], g_c2[8 * NBIN];
__device__ unsigned int g_cnt;

__global__ __launch_bounds__(256) void fused_kernel(
    const float* __restrict__ sl, const float* __restrict__ tl,
    const float* __restrict__ sp, const float* __restrict__ tp,
    const float* __restrict__ W1, const float* __restrict__ b1,
    const float* __restrict__ W2, const float* __restrict__ b2,
    const int*  __restrict__ tg, float* __restrict__ out)
{
    __shared__ float  Ws[2 * O * 2 * FH];          // [W2 | W1]
    __shared__ double sacc[O * 8];
    __shared__ double sSA[8 * NBIN], sSB[8 * NBIN];
    __shared__ int    sc1[8 * NBIN], sc2[8 * NBIN];
    __shared__ double s_ce, s_kl;
    // epilogue scratch
    __shared__ double m_sh[128], p_sh[128];
    __shared__ double matchS[8], pairS[8], D2s[O], E3s[7], E12[2], facc[O * 8];
    __shared__ int s_last;

    const int tid = threadIdx.x;
    const int bid = blockIdx.x;

    if (bid < LBLK) {
        // ================= logits: CE + KL (one warp per row) =================
        if (tid == 0) { s_ce = 0.0; s_kl = 0.0; }
        __syncthreads();

        int row  = bid * 8 + (tid >> 5);
        int lane = tid & 31;
        const float* s = sl + row * NCLS;
        const float* t = tl + row * NCLS;

        float sv[4], tv[4];
#pragma unroll
        for (int i = 0; i < 4; i++) {
            int c = lane + 32 * i;
            bool val = c < NCLS;
            sv[i] = val ? s[c] : -INFINITY;
            tv[i] = val ? t[c] : -INFINITY;
        }
        float smax = fmaxf(fmaxf(sv[0], sv[1]), fmaxf(sv[2], sv[3]));
        float tmax = fmaxf(fmaxf(tv[0], tv[1]), fmaxf(tv[2], tv[3]));
#pragma unroll
        for (int o = 16; o; o >>= 1) {
            smax = fmaxf(smax, __shfl_xor_sync(0xffffffffu, smax, o));
            tmax = fmaxf(tmax, __shfl_xor_sync(0xffffffffu, tmax, o));
        }

        float S1 = 0.f, S4 = 0.f, T4 = 0.f;
        float te[4];
#pragma unroll
        for (int i = 0; i < 4; i++) {
            int c = lane + 32 * i;
            if (c < NCLS) {
                float ds = sv[i] - smax;
                S1 += __expf(ds);
                S4 += __expf(ds * 0.25f);
                te[i] = __expf((tv[i] - tmax) * 0.25f);
                T4 += te[i];
            } else te[i] = 0.f;
        }
#pragma unroll
        for (int o = 16; o; o >>= 1) {
            S1 += __shfl_xor_sync(0xffffffffu, S1, o);
            S4 += __shfl_xor_sync(0xffffffffu, S4, o);
            T4 += __shfl_xor_sync(0xffffffffu, T4, o);
        }
        float lS1 = logf(S1), lS4 = logf(S4), lT4 = logf(T4);
        float invT4 = 1.0f / T4;

        float kl = 0.f;
#pragma unroll
        for (int i = 0; i < 4; i++) {
            int c = lane + 32 * i;
            if (c < NCLS) {
                float a   = (tv[i] - tmax) * 0.25f;
                float q   = te[i] * invT4;
                float slp = (sv[i] - smax) * 0.25f - lS4;
                kl += q * ((a - lT4) - slp);
            }
        }
#pragma unroll
        for (int o = 16; o; o >>= 1) kl += __shfl_down_sync(0xffffffffu, kl, o);

        int label = tg[row * 8];
        int idx = label >> 5;
        float cand = (idx == 0) ? sv[0] : (idx == 1) ? sv[1] : (idx == 2) ? sv[2] : sv[3];
        float slab = __shfl_sync(0xffffffffu, cand, label & 31);

        if (lane == 0) {
            atomicAdd(&s_ce, (double)(smax + lS1) - (double)slab);
            atomicAdd(&s_kl, (double)kl);
        }
        __syncthreads();
        if (tid == 0) { atomicAdd(&g_ce, s_ce); atomicAdd(&g_kl, s_kl); }
    } else {
        // ================= policy: GEMVs + closed-form stats =================
        int pb = bid - LBLK;
        for (int i = tid; i < O * 2 * FH; i += 256) {
            Ws[i] = W2[i];
            Ws[O * 2 * FH + i] = W1[i];
        }
        for (int i = tid; i < O * 8; i += 256) sacc[i] = 0.0;
        if (tid < 8 * NBIN) { sSA[tid] = 0.0; sSB[tid] = 0.0; sc1[tid] = 0; sc2[tid] = 0; }
        __syncthreads();

        int j = pb * 256 + tid;                  // pair index 0..1023
        const float* se  = sp + (2 * j) * FH;    // student even  -> A
        const float* so  = se + FH;              // student odd   -> B
        const float* tee = tp + (2 * j) * FH;    // teacher even  -> A
        const float* to  = tee + FH;             // teacher odd   -> B
        const float* W2s = Ws;
        const float* W1s = Ws + O * 2 * FH;

        float as[O] = {}, bs[O] = {}, at[O] = {}, bt[O] = {};
#pragma unroll
        for (int c = 0; c < FH; c += 4) {
            float4 a = *(const float4*)(se + c);
            float4 b = *(const float4*)(so + c);
            float4 x = *(const float4*)(tee + c);
            float4 y = *(const float4*)(to + c);
#pragma unroll
            for (int k = 0; k < O; k++) {
                const float* w2l = W2s + k * 2 * FH + c;
                const float* w2h = w2l + FH;
                const float* w1l = W1s + k * 2 * FH + c;
                const float* w1h = w1l + FH;
                as[k] += a.x * w2l[0] + a.y * w2l[1] + a.z * w2l[2] + a.w * w2l[3];
                bs[k] += b.x * w2h[0] + b.y * w2h[1] + b.z * w2h[2] + b.w * w2h[3];
                at[k] += x.x * w1l[0] + x.y * w1l[1] + x.z * w1l[2] + x.w * w1l[3];
                bt[k] += y.x * w1h[0] + y.y * w1h[1] + y.z * w1h[2] + y.w * w1h[3];
            }
        }

        // per-k warp reductions in float (u = sB - tB, v = sA - tA)
#pragma unroll
        for (int k = 0; k < O; k++) {
            float u = bs[k] - bt[k];
            float v = as[k] - at[k];
            float r[8];
            r[0] = u;      r[1] = u * u;
            r[2] = v;      r[3] = v * v;
            r[4] = bs[k];  r[5] = as[k];
            r[6] = bs[k] * bs[k];
            r[7] = as[k] * as[k];
#pragma unroll
            for (int q = 0; q < 8; q++) {
#pragma unroll
                for (int o = 16; o; o >>= 1)
                    r[q] += __shfl_down_sync(0xffffffffu, r[q], o);
            }
            if ((tid & 31) == 0) {
#pragma unroll
                for (int q = 0; q < 8; q++) atomicAdd(&sacc[k * 8 + q], (double)r[q]);
            }
        }

        // binned match sums (target col tc pairs with output col tc+1)
        const int* t1r = tg + (2 * j) * 8;
        const int* t2r = t1r + 8;
#pragma unroll
        for (int tc = 0; tc < 8; tc++) {
            int v1 = t1r[tc] & (NBIN - 1);
            int v2 = t2r[tc] & (NBIN - 1);
            atomicAdd(&sSA[tc * NBIN + v1], (double)as[tc + 1]);
            atomicAdd(&sc1[tc * NBIN + v1], 1);
            atomicAdd(&sSB[tc * NBIN + v2], (double)bs[tc + 1]);
            atomicAdd(&sc2[tc * NBIN + v2], 1);
        }
        __syncthreads();

        for (int i = tid; i < O * 8; i += 256) atomicAdd(&g_acc[i], sacc[i]);
        if (tid < 8 * NBIN) {
            atomicAdd(&g_SA[tid], sSA[tid]);
            atomicAdd(&g_SB[tid], sSB[tid]);
            atomicAdd(&g_c1[tid], sc1[tid]);
            atomicAdd(&g_c2[tid], sc2[tid]);
        }
    }

    // ================= last-block epilogue =================
    __threadfence();
    if (tid == 0)
        s_last = (atomicAdd(&g_cnt, 1u) == (unsigned)(NBLOCKS - 1));
    __syncthreads();
    if (!s_last) return;
    __threadfence();

    volatile double* vacc = g_acc;
    volatile double* vSA  = g_SA;
    volatile double* vSB  = g_SB;
    volatile int*    vc1  = g_c1;
    volatile int*    vc2  = g_c2;

    // phase A: per-bin pair sums (128 thr) + acc copy (72 thr)
    if (tid < 128) {
        int tc = tid >> 4;
        double c1 = (double)vc1[tid];
        double c2 = (double)vc2[tid];
        double bias = (double)b2[tc + 1];
        m_sh[tid] = c1 * vSB[tid] + c2 * vSA[tid] + c1 * c2 * bias;
        p_sh[tid] = c1 * c2;
    } else if (tid - 128 < O * 8) {
        facc[tid - 128] = vacc[tid - 128];
    }
    __syncthreads();

    const double n = 1024.0, N2 = n * n;

    // phase B: per-tc bin sums (8 thr) + per-k D2 (9 thr, disjoint range)
    if (tid < 8) {
        double ms = 0.0, ps = 0.0;
#pragma unroll
        for (int v = 0; v < NBIN; v++) { ms += m_sh[tid * NBIN + v]; ps += p_sh[tid * NBIN + v]; }
        matchS[tid] = ms; pairS[tid] = ps;
    } else if (tid >= 32 && tid < 32 + O) {
        int k = tid - 32;
        double Su = facc[k*8+0], Su2 = facc[k*8+1], Sv = facc[k*8+2], Sv2 = facc[k*8+3];
        double ck = (double)b2[k] - (double)b1[k];
        D2s[k] = n * Su2 + n * Sv2 + 2.0 * Su * Sv
               + 2.0 * ck * n * (Su + Sv) + N2 * ck * ck;
    }
    __syncthreads();

    // phase C: E3 per policy column (7 thr), E1 (1 thr), E2 (1 thr)
    if (tid < 7) {
        int k = tid + 2, t = tid + 1;
        double Sb = facc[k*8+4], Sa = facc[k*8+5], Sb2 = facc[k*8+6], Sa2 = facc[k*8+7];
        double ck = (double)b2[k];
        double Sp2 = n * Sb2 + n * Sa2 + 2.0 * Sb * Sa
                   + 2.0 * ck * n * (Sb + Sa) + N2 * ck * ck;
        double Sp  = n * (Sb + Sa) + N2 * ck;
        double Spg = 2.0 * matchS[t] - Sp;
        E3s[tid] = Sp2 - 2.0 * Spg + N2;
    } else if (tid == 8) {
        double gId = (double)((1.0f / 1023.0f + 1.0f) - 1.0f / 1023.0f);
        double Sb0 = facc[0*8+4], Sa0 = facc[0*8+5];
        E12[0] = (n * gId * log(gId) - gId * (Sb0 + Sa0 + n * (double)b2[0])) / N2;
    } else if (tid == 9) {
        double gCp = (double)((1.0f / 99.0f + 1.0f) - 1.0f / 99.0f);
        E12[1] = 0.5 * (pairS[0] * gCp * log(gCp) - gCp * matchS[0]) / N2;
    }
    __syncthreads();

    // phase D: scalar combine
    if (tid == 0) {
        double sumDP = 0.0;
#pragma unroll
        for (int k = 2; k < O; k++) sumDP += D2s[k];
        double klp = D2s[0] / N2 + 0.5 * D2s[1] / N2 + 0.001 * sumDP / (N2 * 7.0);

        double E3 = 0.0;
#pragma unroll
        for (int m = 0; m < 7; m++) E3 += E3s[m];
        E3 *= 0.001 / (N2 * 7.0);

        double ce = *(volatile double*)&g_ce;
        double kl = *(volatile double*)&g_kl;
        double policy = klp + E12[0] + E12[1] + E3;
        out[0] = (float)(ce / (double)BATCH
                       + kl / ((double)BATCH * (double)NCLS) * 16.0
                       + policy);
    }
    __syncthreads();

    // reset scratch for next replay (device globals stay zeroed between runs)
    if (tid < O * 8) g_acc[tid] = 0.0;
    if (tid < 8 * NBIN) { g_SA[tid] = 0.0; g_SB[tid] = 0.0; g_c1[tid] = 0; g_c2[tid] = 0; }
    if (tid == 0) { g_ce = 0.0; g_kl = 0.0; g_cnt = 0u; }
}

// ---------------- launch ----------------
extern "C" void kernel_launch(void* const* d_in, const int* in_sizes, int n_in,
                              void* d_out, int out_size)
{
    const float* sl = (const float*)d_in[0];   // student_logits (2048,100)
    const float* tl = (const float*)d_in[1];   // teacher_logits (2048,100)
    const float* sp = (const float*)d_in[2];   // student_policy (2048,64)
    const float* tp = (const float*)d_in[3];   // teacher_policy (2048,64)
    const float* W1 = (const float*)d_in[4];   // (9,128)
    const float* b1 = (const float*)d_in[5];   // (9,)
    const float* W2 = (const float*)d_in[6];   // (9,128)
    const float* b2 = (const float*)d_in[7];   // (9,)
    const int*   tg = (const int*)d_in[8];     // (2048,1,8)

    fused_kernel<<<NBLOCKS, 256>>>(sl, tl, sp, tp, W1, b1, W2, b2, tg, (float*)d_out);
}

// round 4
// speedup vs baseline: 2.0630x; 1.5906x over previous
#include <cuda_runtime.h>
#include <math.h>
#include <stdint.h>

#define BATCH    2048
#define NCLS     100
#define FH       64        // FEATURE_NUMS/2
#define O        9         // POLICY_NUMS + 2
#define NBIN     16
#define LBLK     256       // logits blocks (8 rows each)
#define PBLK     16        // policy blocks (64 pairs each, 4 threads/pair)
#define NBLOCKS  (LBLK + PBLK)
#define WSZ      (O * 2 * FH)   // 1152 floats per weight matrix

// ---------------- scratch (device globals; zero at load, re-zeroed each run) ---
__device__ double g_ce, g_kl;
// per-k stats [k][q], q: 0 Su,1 Su2,2 Sv,3 Sv2,4 Sb,5 Sa,6 Sb2,7 Sa2
__device__ double g_acc[O * 8];
__device__ double g_SA[8 * NBIN], g_SB[8 * NBIN];
__device__ int    g_c1[8 * NBIN], g_c2[8 * NBIN];
__device__ unsigned int g_cnt;

__global__ __launch_bounds__(256) void fused_kernel(
    const float* __restrict__ sl, const float* __restrict__ tl,
    const float* __restrict__ sp, const float* __restrict__ tp,
    const float* __restrict__ W1, const float* __restrict__ b1,
    const float* __restrict__ W2, const float* __restrict__ b2,
    const int*  __restrict__ tg, float* __restrict__ out)
{
    __shared__ float  Ws[2 * WSZ];                 // [W2 | W1]
    __shared__ double sacc[O * 8];
    __shared__ double sSA[8 * NBIN], sSB[8 * NBIN];
    __shared__ int    sc1[8 * NBIN], sc2[8 * NBIN];
    __shared__ double s_ce, s_kl;
    __shared__ double m_sh[128], p_sh[128];
    __shared__ double matchS[8], pairS[8], D2s[O], E3s[7], E12[2], facc[O * 8];
    __shared__ int s_last;

    const int tid = threadIdx.x;
    const int bid = blockIdx.x;

    if (bid < LBLK) {
        // ================= logits: CE + KL (one warp per row) =================
        if (tid == 0) { s_ce = 0.0; s_kl = 0.0; }
        __syncthreads();

        int row  = bid * 8 + (tid >> 5);
        int lane = tid & 31;
        const float* s = sl + row * NCLS;
        const float* t = tl + row * NCLS;

        float sv[4], tv[4];
#pragma unroll
        for (int i = 0; i < 4; i++) {
            int c = lane + 32 * i;
            bool val = c < NCLS;
            sv[i] = val ? s[c] : -INFINITY;
            tv[i] = val ? t[c] : -INFINITY;
        }
        float smax = fmaxf(fmaxf(sv[0], sv[1]), fmaxf(sv[2], sv[3]));
        float tmax = fmaxf(fmaxf(tv[0], tv[1]), fmaxf(tv[2], tv[3]));
#pragma unroll
        for (int o = 16; o; o >>= 1) {
            smax = fmaxf(smax, __shfl_xor_sync(0xffffffffu, smax, o));
            tmax = fmaxf(tmax, __shfl_xor_sync(0xffffffffu, tmax, o));
        }

        // single pass: S1, S4, T4 and KL cross-sums U = sum(te*a), V = sum(te*s4)
        float S1 = 0.f, S4 = 0.f, T4 = 0.f, U = 0.f, V = 0.f;
#pragma unroll
        for (int i = 0; i < 4; i++) {
            int c = lane + 32 * i;
            if (c < NCLS) {
                float ds  = sv[i] - smax;
                float s4a = ds * 0.25f;
                float a   = (tv[i] - tmax) * 0.25f;
                float te  = __expf(a);
                S1 += __expf(ds);
                S4 += __expf(s4a);
                T4 += te;
                U  += te * a;
                V  += te * s4a;
            }
        }
#pragma unroll
        for (int o = 16; o; o >>= 1) {
            S1 += __shfl_down_sync(0xffffffffu, S1, o);
            S4 += __shfl_down_sync(0xffffffffu, S4, o);
            T4 += __shfl_down_sync(0xffffffffu, T4, o);
            U  += __shfl_down_sync(0xffffffffu, U,  o);
            V  += __shfl_down_sync(0xffffffffu, V,  o);
        }

        // CE row: logsumexp(s) - s[label]  (slab shuffle involves all lanes)
        int label = tg[row * 8];
        int idx = label >> 5;
        float cand = (idx == 0) ? sv[0] : (idx == 1) ? sv[1] : (idx == 2) ? sv[2] : sv[3];
        float slab = __shfl_sync(0xffffffffu, cand, label & 31);

        if (lane == 0) {
            float lS1 = logf(S1), lS4 = logf(S4), lT4 = logf(T4);
            float kl = (U - V) / T4 + lS4 - lT4;   // sum_c q*(logq - slogp)
            atomicAdd(&s_ce, (double)(smax + lS1) - (double)slab);
            atomicAdd(&s_kl, (double)kl);
        }
        __syncthreads();
        if (tid == 0) { atomicAdd(&g_ce, s_ce); atomicAdd(&g_kl, s_kl); }
    } else {
        // ============ policy: GEMVs, 4 threads per pair (FH split 4x) ============
        int pb = bid - LBLK;                       // 0..15
        for (int i = tid; i < WSZ; i += 256) {
            Ws[i] = W2[i];
            Ws[WSZ + i] = W1[i];
        }
        for (int i = tid; i < O * 8; i += 256) sacc[i] = 0.0;
        if (tid < 8 * NBIN) { sSA[tid] = 0.0; sSB[tid] = 0.0; sc1[tid] = 0; sc2[tid] = 0; }
        __syncthreads();

        int wid  = tid >> 5;
        int lane = tid & 31;
        int sub  = lane & 3;                       // feature quarter
        int j    = pb * 64 + wid * 8 + (lane >> 2);// pair index 0..1023
        int c0   = sub * 16;

        const float* se  = sp + (2 * j) * FH + c0;     // student even  -> A
        const float* so  = se + FH;                    // student odd   -> B
        const float* tee = tp + (2 * j) * FH + c0;     // teacher even  -> A
        const float* to  = tee + FH;                   // teacher odd   -> B

        float as[O] = {}, bs[O] = {}, at[O] = {}, bt[O] = {};
#pragma unroll
        for (int cc = 0; cc < 16; cc += 4) {
            float4 a = *(const float4*)(se + cc);
            float4 b = *(const float4*)(so + cc);
            float4 x = *(const float4*)(tee + cc);
            float4 y = *(const float4*)(to + cc);
#pragma unroll
            for (int k = 0; k < O; k++) {
                const float* w2l = Ws + k * 2 * FH + c0 + cc;
                const float* w2h = w2l + FH;
                const float* w1l = Ws + WSZ + k * 2 * FH + c0 + cc;
                const float* w1h = w1l + FH;
                as[k] += a.x * w2l[0] + a.y * w2l[1] + a.z * w2l[2] + a.w * w2l[3];
                bs[k] += b.x * w2h[0] + b.y * w2h[1] + b.z * w2h[2] + b.w * w2h[3];
                at[k] += x.x * w1l[0] + x.y * w1l[1] + x.z * w1l[2] + x.w * w1l[3];
                bt[k] += y.x * w1h[0] + y.y * w1h[1] + y.z * w1h[2] + y.w * w1h[3];
            }
        }
        // combine quarters: head lane (sub==0) of each group gets the full dot
#pragma unroll
        for (int k = 0; k < O; k++) {
            as[k] += __shfl_down_sync(0xffffffffu, as[k], 2);
            as[k] += __shfl_down_sync(0xffffffffu, as[k], 1);
            bs[k] += __shfl_down_sync(0xffffffffu, bs[k], 2);
            bs[k] += __shfl_down_sync(0xffffffffu, bs[k], 1);
            at[k] += __shfl_down_sync(0xffffffffu, at[k], 2);
            at[k] += __shfl_down_sync(0xffffffffu, at[k], 1);
            bt[k] += __shfl_down_sync(0xffffffffu, bt[k], 2);
            bt[k] += __shfl_down_sync(0xffffffffu, bt[k], 1);
        }
        bool head = (sub == 0);

        // per-k stats: heads hold values, others contribute 0; 3-level reduce
#pragma unroll
        for (int k = 0; k < O; k++) {
            float u = bs[k] - bt[k];
            float v = as[k] - at[k];
            float r[8];
            r[0] = head ? u : 0.f;        r[1] = head ? u * u : 0.f;
            r[2] = head ? v : 0.f;        r[3] = head ? v * v : 0.f;
            r[4] = head ? bs[k] : 0.f;    r[5] = head ? as[k] : 0.f;
            r[6] = head ? bs[k] * bs[k] : 0.f;
            r[7] = head ? as[k] * as[k] : 0.f;
#pragma unroll
            for (int q = 0; q < 8; q++) {
                r[q] += __shfl_down_sync(0xffffffffu, r[q], 16);
                r[q] += __shfl_down_sync(0xffffffffu, r[q], 8);
                r[q] += __shfl_down_sync(0xffffffffu, r[q], 4);
            }
            if (lane == 0) {
#pragma unroll
                for (int q = 0; q < 8; q++) atomicAdd(&sacc[k * 8 + q], (double)r[q]);
            }
        }

        // binned match sums (head lanes only; target col tc <-> output col tc+1)
        if (head) {
            const int* t1r = tg + (2 * j) * 8;
            const int* t2r = t1r + 8;
#pragma unroll
            for (int tc = 0; tc < 8; tc++) {
                int v1 = t1r[tc] & (NBIN - 1);
                int v2 = t2r[tc] & (NBIN - 1);
                atomicAdd(&sSA[tc * NBIN + v1], (double)as[tc + 1]);
                atomicAdd(&sc1[tc * NBIN + v1], 1);
                atomicAdd(&sSB[tc * NBIN + v2], (double)bs[tc + 1]);
                atomicAdd(&sc2[tc * NBIN + v2], 1);
            }
        }
        __syncthreads();

        for (int i = tid; i < O * 8; i += 256) atomicAdd(&g_acc[i], sacc[i]);
        if (tid < 8 * NBIN) {
            atomicAdd(&g_SA[tid], sSA[tid]);
            atomicAdd(&g_SB[tid], sSB[tid]);
            atomicAdd(&g_c1[tid], sc1[tid]);
            atomicAdd(&g_c2[tid], sc2[tid]);
        }
    }

    // ================= last-block epilogue =================
    __threadfence();
    if (tid == 0)
        s_last = (atomicAdd(&g_cnt, 1u) == (unsigned)(NBLOCKS - 1));
    __syncthreads();
    if (!s_last) return;
    __threadfence();

    volatile double* vacc = g_acc;
    volatile double* vSA  = g_SA;
    volatile double* vSB  = g_SB;
    volatile int*    vc1  = g_c1;
    volatile int*    vc2  = g_c2;

    const double n = 1024.0;
    const double INV_N2 = 1.0 / (1024.0 * 1024.0);

    // phase A: per-bin pair sums (128 thr) + acc copy (72 thr)
    if (tid < 128) {
        int tc = tid >> 4;
        double c1 = (double)vc1[tid];
        double c2 = (double)vc2[tid];
        double bias = (double)b2[tc + 1];
        m_sh[tid] = c1 * vSB[tid] + c2 * vSA[tid] + c1 * c2 * bias;
        p_sh[tid] = c1 * c2;
    } else if (tid - 128 < O * 8) {
        facc[tid - 128] = vacc[tid - 128];
    }
    __syncthreads();

    // phase B: per-tc bin sums (8 thr) + per-k D2 (9 thr, disjoint range)
    if (tid < 8) {
        double ms = 0.0, ps = 0.0;
#pragma unroll
        for (int v = 0; v < NBIN; v++) { ms += m_sh[tid * NBIN + v]; ps += p_sh[tid * NBIN + v]; }
        matchS[tid] = ms; pairS[tid] = ps;
    } else if (tid >= 32 && tid < 32 + O) {
        int k = tid - 32;
        double Su = facc[k*8+0], Su2 = facc[k*8+1], Sv = facc[k*8+2], Sv2 = facc[k*8+3];
        double ck = (double)b2[k] - (double)b1[k];
        D2s[k] = n * Su2 + n * Sv2 + 2.0 * Su * Sv
               + 2.0 * ck * n * (Su + Sv) + (n * n) * ck * ck;
    }
    __syncthreads();

    // phase C: E3 per policy column (7 thr), E1, E2
    if (tid < 7) {
        int k = tid + 2, t = tid + 1;
        double Sb = facc[k*8+4], Sa = facc[k*8+5], Sb2 = facc[k*8+6], Sa2 = facc[k*8+7];
        double ck = (double)b2[k];
        double Sp2 = n * Sb2 + n * Sa2 + 2.0 * Sb * Sa
                   + 2.0 * ck * n * (Sb + Sa) + (n * n) * ck * ck;
        double Sp  = n * (Sb + Sa) + (n * n) * ck;
        double Spg = 2.0 * matchS[t] - Sp;
        E3s[tid] = Sp2 - 2.0 * Spg + (n * n);
    } else if (tid == 8) {
        // gId == 1 +/- few float ULP  =>  log(gId) == gId - 1 to ~1e-14 abs
        double gId = (double)((1.0f / 1023.0f + 1.0f) - 1.0f / 1023.0f);
        double Sb0 = facc[0*8+4], Sa0 = facc[0*8+5];
        E12[0] = (n * gId * (gId - 1.0) - gId * (Sb0 + Sa0 + n * (double)b2[0])) * INV_N2;
    } else if (tid == 9) {
        double gCp = (double)((1.0f / 99.0f + 1.0f) - 1.0f / 99.0f);
        E12[1] = 0.5 * (pairS[0] * gCp * (gCp - 1.0) - gCp * matchS[0]) * INV_N2;
    }
    __syncthreads();

    // phase D: scalar combine (all divides folded into constant multiplies)
    if (tid == 0) {
        double sumDP = 0.0;
#pragma unroll
        for (int k = 2; k < O; k++) sumDP += D2s[k];
        double klp = D2s[0] * INV_N2 + 0.5 * D2s[1] * INV_N2
                   + sumDP * (0.001 * INV_N2 / 7.0);

        double E3 = 0.0;
#pragma unroll
        for (int m = 0; m < 7; m++) E3 += E3s[m];
        E3 *= 0.001 * INV_N2 / 7.0;

        double ce = *(volatile double*)&g_ce;
        double kl = *(volatile double*)&g_kl;
        double policy = klp + E12[0] + E12[1] + E3;
        out[0] = (float)(ce * (1.0 / (double)BATCH)
                       + kl * (16.0 / ((double)BATCH * (double)NCLS))
                       + policy);
    }
    __syncthreads();

    // reset scratch for next replay
    if (tid < O * 8) g_acc[tid] = 0.0;
    if (tid < 8 * NBIN) { g_SA[tid] = 0.0; g_SB[tid] = 0.0; g_c1[tid] = 0; g_c2[tid] = 0; }
    if (tid == 0) { g_ce = 0.0; g_kl = 0.0; g_cnt = 0u; }
}

// ---------------- launch ----------------
extern "C" void kernel_launch(void* const* d_in, const int* in_sizes, int n_in,
                              void* d_out, int out_size)
{
    const float* sl = (const float*)d_in[0];   // student_logits (2048,100)
    const float* tl = (const float*)d_in[1];   // teacher_logits (2048,100)
    const float* sp = (const float*)d_in[2];   // student_policy (2048,64)
    const float* tp = (const float*)d_in[3];   // teacher_policy (2048,64)
    const float* W1 = (const float*)d_in[4];   // (9,128)
    const float* b1 = (const float*)d_in[5];   // (9,)
    const float* W2 = (const float*)d_in[6];   // (9,128)
    const float* b2 = (const float*)d_in[7];   // (9,)
    const int*   tg = (const int*)d_in[8];     // (2048,1,8)

    fused_kernel<<<NBLOCKS, 256>>>(sl, tl, sp, tp, W1, b1, W2, b2, tg, (float*)d_out);
}